// round 9
// baseline (speedup 1.0000x reference)
#include <cuda_runtime.h>
#include <float.h>
#include <stdint.h>

#define Bb 2
#define Hh 16
#define Ss 2048
#define Dd 64
#define BM 128          // query rows per CTA (4 warps x 32 rows)
#define BN 64           // key tile
#define NTHREADS 128
#define NTILES (Ss / BN)   // 32

// ---- shared memory layout (float offsets) ----
// K/V tiles stored FRAGMENT-PACKED: [kg (8)][lane (32)][20]  (16 used + 4 pad)
// lane stride 20 floats -> LDS.128 at lane*20+{0,4,8,12} is bank-conflict-free.
// DOUBLE BUFFERED: two tile buffers, ping-pong per iteration.
#define LST 20
#define KGSZ (32 * LST)                  // 640 floats per key-group
#define TILEK (8 * KGSZ)                 // 5120 floats (K half)
#define TILESZ (16 * KGSZ)               // 10240 floats (K+V)
#define OFF_MASK 0                       // [2048] additive mask row
#define OFF_BUF0 2048
#define OFF_BUF1 (OFF_BUF0 + TILESZ)     // 12288
#define SMEM_FLOATS (OFF_BUF1 + TILESZ)  // 22528 floats = 90112 B

// ---------------------------------------------------------------------------
// tf32 helpers
// ---------------------------------------------------------------------------
__device__ __forceinline__ float rna(float x) {
    uint32_t u;
    asm("cvt.rna.tf32.f32 %0, %1;" : "=r"(u) : "f"(x));
    return __uint_as_float(u);
}

// D += A*B, m16n8k8 tf32 (PTX fragment layouts)
__device__ __forceinline__ void mma8(float* d, const uint32_t* a,
                                     uint32_t b0, uint32_t b1) {
    asm volatile(
        "mma.sync.aligned.m16n8k8.row.col.f32.tf32.tf32.f32 "
        "{%0,%1,%2,%3},{%4,%5,%6,%7},{%8,%9},{%0,%1,%2,%3};"
        : "+f"(d[0]), "+f"(d[1]), "+f"(d[2]), "+f"(d[3])
        : "r"(a[0]), "r"(a[1]), "r"(a[2]), "r"(a[3]), "r"(b0), "r"(b1));
}

// ---------------------------------------------------------------------------
// Mask prepass (jax bool may be byte-bool or int32; detect then expand)
// ---------------------------------------------------------------------------
__device__ int   g_mask_is_i32;
__device__ float g_maskadd[Bb * Ss];

__global__ void detect_mask_kernel(const unsigned int* __restrict__ mask_w) {
    __shared__ int bad;
    if (threadIdx.x == 0) bad = 0;
    __syncthreads();
    for (int idx = threadIdx.x; idx < (Bb * Ss) / 4; idx += blockDim.x)
        if (mask_w[idx] > 1u) bad = 1;
    __syncthreads();
    if (threadIdx.x == 0) g_mask_is_i32 = bad ? 0 : 1;
}
__global__ void expand_mask_kernel(const void* __restrict__ mask) {
    int idx = blockIdx.x * blockDim.x + threadIdx.x;
    if (idx >= Bb * Ss) return;
    int mval = g_mask_is_i32 ? ((const int*)mask)[idx]
                             : (int)((const unsigned char*)mask)[idx];
    g_maskadd[idx] = mval ? 0.0f : -FLT_MAX;
}

// ---------------------------------------------------------------------------
// Scatter a buffered K/V tile (registers) into fragment-packed smem layout.
// K elem [key][d] -> lane 4*(key&7)+(d&3), slot 2*(d>>3)+((d>>2)&1)
// V rows PERMUTED: actual row r -> virtual vk = (r&1)? (r>>1)+4 : r>>1
//   so the MMA1 D-fragment feeds MMA2's A-fragment directly (no shuffles).
// ---------------------------------------------------------------------------
__device__ __forceinline__ void scatter_tile(float* s, int bufoff,
                                             const float4* kbuf,
                                             const float4* vbuf, int tid) {
#pragma unroll
    for (int it = 0; it < 8; it++) {
        const int idx = tid + it * NTHREADS;     // 0..1023
        const int row = idx >> 4;
        const int c   = (idx & 15) * 4;
        const int kg  = row >> 3;
        const int r   = row & 7;
        {
            const int k0 = c >> 3, hf = (c >> 2) & 1;
            float* kb = &s[bufoff + kg * KGSZ + r * (4 * LST) + k0 * 2 + hf];
            kb[0 * LST] = rna(kbuf[it].x);
            kb[1 * LST] = rna(kbuf[it].y);
            kb[2 * LST] = rna(kbuf[it].z);
            kb[3 * LST] = rna(kbuf[it].w);
        }
        {
            const int vk = (r & 1) ? ((r >> 1) + 4) : (r >> 1);
            const int tv = vk & 3, hv = (vk >> 2) & 1, n0 = c >> 3;
            float* vb = &s[bufoff + TILEK + kg * KGSZ + (c & 7) * (4 * LST)
                           + tv * LST + n0 * 2 + hv];
            vb[0 * (4 * LST)] = rna(vbuf[it].x);
            vb[1 * (4 * LST)] = rna(vbuf[it].y);
            vb[2 * (4 * LST)] = rna(vbuf[it].z);
            vb[3 * (4 * LST)] = rna(vbuf[it].w);
        }
    }
}

// ---------------------------------------------------------------------------
// Main attention kernel: 32 rows/warp, double-buffered smem (1 barrier/tile),
// split MMA1 chains (ILP 4), permuted-V shuffle-free P feed, prefetch pipeline.
// ---------------------------------------------------------------------------
__global__ void __launch_bounds__(NTHREADS)
attn_kernel(const float* __restrict__ q,
            const float* __restrict__ k,
            const float* __restrict__ v,
            const float* __restrict__ taus,
            const float* __restrict__ bias,
            float* __restrict__ out)
{
    extern __shared__ float s[];

    const int tid  = threadIdx.x;
    const int wid  = tid >> 5;
    const int lane = tid & 31;
    const int g    = lane >> 2;    // groupID (row within fragment)
    const int tig  = lane & 3;     // threadID_in_group

    const int itile = blockIdx.x;
    const int h     = blockIdx.y;
    const int b     = blockIdx.z;

    const int   plane = (b * Hh + h) * Ss;
    const float tau   = taus[h];
    const int   rowb  = wid * 32;               // warp's first local row
    const int   qgA   = itile * BM + rowb + g;  // row-block A, g-half row
    const int   qgB   = qgA + 16;               // row-block B

    // ---- stage mask row ----
    {
        const float* madd = g_maskadd + b * Ss;
        for (int x = tid; x < Ss; x += NTHREADS) s[OFF_MASK + x] = madd[x];
    }

    // ---- load Q fragments for both row-blocks (one-time, tf32-rounded) ----
    uint32_t qfA[8][4], qfB[8][4];
    {
        const float* qa0 = q + (size_t)(plane + qgA) * Dd;
        const float* qa1 = qa0 + 8 * Dd;
        const float* qb0 = q + (size_t)(plane + qgB) * Dd;
        const float* qb1 = qb0 + 8 * Dd;
#pragma unroll
        for (int k0 = 0; k0 < 8; k0++) {
            qfA[k0][0] = __float_as_uint(rna(qa0[k0 * 8 + tig]));
            qfA[k0][1] = __float_as_uint(rna(qa1[k0 * 8 + tig]));
            qfA[k0][2] = __float_as_uint(rna(qa0[k0 * 8 + tig + 4]));
            qfA[k0][3] = __float_as_uint(rna(qa1[k0 * 8 + tig + 4]));
            qfB[k0][0] = __float_as_uint(rna(qb0[k0 * 8 + tig]));
            qfB[k0][1] = __float_as_uint(rna(qb1[k0 * 8 + tig]));
            qfB[k0][2] = __float_as_uint(rna(qb0[k0 * 8 + tig + 4]));
            qfB[k0][3] = __float_as_uint(rna(qb1[k0 * 8 + tig + 4]));
        }
    }

    float oaccA[8][4], oaccB[8][4];
#pragma unroll
    for (int n0 = 0; n0 < 8; n0++)
#pragma unroll
        for (int x = 0; x < 4; x++) { oaccA[n0][x] = 0.f; oaccB[n0][x] = 0.f; }
    float lA0 = 0.f, lA1 = 0.f, lB0 = 0.f, lB1 = 0.f;

    const float4* ksrc = (const float4*)(k + (size_t)plane * Dd);
    const float4* vsrc = (const float4*)(v + (size_t)plane * Dd);
    const float* browA0 = bias + ((size_t)b * Ss + qgA) * Ss;
    const float* browA1 = browA0 + 8 * Ss;
    const float* browB0 = browA0 + 16 * Ss;
    const float* browB1 = browA0 + 24 * Ss;

    // ---- pipeline prologue: tile 0 -> buf0; tile 1 -> registers ----
    float4 kbuf[8], vbuf[8];
#pragma unroll
    for (int it = 0; it < 8; it++) {
        kbuf[it] = ksrc[tid + it * NTHREADS];
        vbuf[it] = vsrc[tid + it * NTHREADS];
    }
    scatter_tile(s, OFF_BUF0, kbuf, vbuf, tid);
    __syncthreads();
#pragma unroll
    for (int it = 0; it < 8; it++) {
        kbuf[it] = ksrc[BN * 16 + tid + it * NTHREADS];
        vbuf[it] = vsrc[BN * 16 + tid + it * NTHREADS];
    }

    for (int t = 0; t < NTILES; t++) {
        const int curoff = (t & 1) ? OFF_BUF1 : OFF_BUF0;
        const int nxtoff = (t & 1) ? OFF_BUF0 : OFF_BUF1;

        // ---- scatter tile t+1 into the other buffer (no barrier needed:
        //      that buffer was last read in iter t-1, before the last barrier;
        //      compute below reads only curoff) ----
        if (t + 1 < NTILES)
            scatter_tile(s, nxtoff, kbuf, vbuf, tid);

        // ---- prefetch tile t+2 (a full tile of compute hides the latency) ----
        if (t + 2 < NTILES) {
            const int base = (t + 2) * BN * 16;   // float4 index
#pragma unroll
            for (int it = 0; it < 8; it++) {
                kbuf[it] = ksrc[base + tid + it * NTHREADS];
                vbuf[it] = vsrc[base + tid + it * NTHREADS];
            }
        }

        const int j0 = t * BN;

        // ---- stream over 8-key groups ----
#pragma unroll
        for (int kg = 0; kg < 8; kg++) {
            // K fragments: 4x LDS.128, conflict-free (stride 20 floats/lane)
            float kfr[16];
            {
                const float4* kp =
                    (const float4*)&s[curoff + kg * KGSZ + lane * LST];
                *(float4*)&kfr[0]  = kp[0];
                *(float4*)&kfr[4]  = kp[1];
                *(float4*)&kfr[8]  = kp[2];
                *(float4*)&kfr[12] = kp[3];
            }

            // MMA1: S(32x8) = Q(32x64) @ K_kg^T — split accumulator chains
            // (depth 4, 4 independent chains) for ILP.
            float saA[4] = {0.f, 0.f, 0.f, 0.f};
            float saB[4] = {0.f, 0.f, 0.f, 0.f};
            float sbA[4] = {0.f, 0.f, 0.f, 0.f};
            float sbB[4] = {0.f, 0.f, 0.f, 0.f};
#pragma unroll
            for (int k0 = 0; k0 < 4; k0++) {
                uint32_t b0 = __float_as_uint(kfr[2 * k0]);
                uint32_t b1 = __float_as_uint(kfr[2 * k0 + 1]);
                mma8(saA, qfA[k0], b0, b1);
                mma8(saB, qfB[k0], b0, b1);
                uint32_t c0 = __float_as_uint(kfr[2 * k0 + 8]);
                uint32_t c1 = __float_as_uint(kfr[2 * k0 + 9]);
                mma8(sbA, qfA[k0 + 4], c0, c1);
                mma8(sbB, qfB[k0 + 4], c0, c1);
            }
#pragma unroll
            for (int x = 0; x < 4; x++) { saA[x] += sbA[x]; saB[x] += sbB[x]; }

            // softmax: scale + mask + tau*bias + exp (both row-blocks)
            const int jl  = kg * 8 + tig * 2;
            const int jgl = j0 + jl;
            float2 mk = *(const float2*)&s[OFF_MASK + jgl];
            float2 biA0 = *(const float2*)&browA0[jgl];
            float2 biA1 = *(const float2*)&browA1[jgl];
            float2 biB0 = *(const float2*)&browB0[jgl];
            float2 biB1 = *(const float2*)&browB1[jgl];
            // masked: x*0.125 + (-FLT_MAX) -> -FLT_MAX; __expf(-FLT_MAX) == 0.
            float pA0 = __expf(fmaf(saA[0], 0.125f, mk.x) - tau * biA0.x);
            float pA1 = __expf(fmaf(saA[1], 0.125f, mk.y) - tau * biA0.y);
            float pA2 = __expf(fmaf(saA[2], 0.125f, mk.x) - tau * biA1.x);
            float pA3 = __expf(fmaf(saA[3], 0.125f, mk.y) - tau * biA1.y);
            float pB0 = __expf(fmaf(saB[0], 0.125f, mk.x) - tau * biB0.x);
            float pB1 = __expf(fmaf(saB[1], 0.125f, mk.y) - tau * biB0.y);
            float pB2 = __expf(fmaf(saB[2], 0.125f, mk.x) - tau * biB1.x);
            float pB3 = __expf(fmaf(saB[3], 0.125f, mk.y) - tau * biB1.y);
            lA0 += pA0 + pA1;  lA1 += pA2 + pA3;
            lB0 += pB0 + pB1;  lB1 += pB2 + pB3;

            // D-fragment used directly as A-fragment (V rows pre-permuted)
            uint32_t aA[4], aB[4];
            aA[0] = __float_as_uint(rna(pA0));
            aA[1] = __float_as_uint(rna(pA2));
            aA[2] = __float_as_uint(rna(pA1));
            aA[3] = __float_as_uint(rna(pA3));
            aB[0] = __float_as_uint(rna(pB0));
            aB[1] = __float_as_uint(rna(pB2));
            aB[2] = __float_as_uint(rna(pB1));
            aB[3] = __float_as_uint(rna(pB3));

            // V fragments: 4x LDS.128, conflict-free
            float vfr[16];
            {
                const float4* vp =
                    (const float4*)&s[curoff + TILEK + kg * KGSZ + lane * LST];
                *(float4*)&vfr[0]  = vp[0];
                *(float4*)&vfr[4]  = vp[1];
                *(float4*)&vfr[8]  = vp[2];
                *(float4*)&vfr[12] = vp[3];
            }

            // MMA2: O(32x64) += P_kg(32x8) @ V_kg(8x64)
#pragma unroll
            for (int n0 = 0; n0 < 8; n0++) {
                uint32_t b0 = __float_as_uint(vfr[2 * n0]);
                uint32_t b1 = __float_as_uint(vfr[2 * n0 + 1]);
                mma8(oaccA[n0], aA, b0, b1);
                mma8(oaccB[n0], aB, b0, b1);
            }
        }
        __syncthreads();   // single barrier per tile (ping-pong buffers)
    }

    // ---- reduce l across the 4 lanes sharing each row ----
    lA0 += __shfl_xor_sync(0xffffffffu, lA0, 1);
    lA0 += __shfl_xor_sync(0xffffffffu, lA0, 2);
    lA1 += __shfl_xor_sync(0xffffffffu, lA1, 1);
    lA1 += __shfl_xor_sync(0xffffffffu, lA1, 2);
    lB0 += __shfl_xor_sync(0xffffffffu, lB0, 1);
    lB0 += __shfl_xor_sync(0xffffffffu, lB0, 2);
    lB1 += __shfl_xor_sync(0xffffffffu, lB1, 1);
    lB1 += __shfl_xor_sync(0xffffffffu, lB1, 2);
    const float invA0 = 1.0f / lA0;
    const float invA1 = 1.0f / lA1;
    const float invB0 = 1.0f / lB0;
    const float invB1 = 1.0f / lB1;

    // ---- normalize + write O ----
    float* oA0 = out + (size_t)(plane + qgA) * Dd;
    float* oA1 = oA0 + 8 * Dd;
    float* oB0 = out + (size_t)(plane + qgB) * Dd;
    float* oB1 = oB0 + 8 * Dd;
#pragma unroll
    for (int n0 = 0; n0 < 8; n0++) {
        *(float2*)&oA0[n0 * 8 + 2 * tig] =
            make_float2(oaccA[n0][0] * invA0, oaccA[n0][1] * invA0);
        *(float2*)&oA1[n0 * 8 + 2 * tig] =
            make_float2(oaccA[n0][2] * invA1, oaccA[n0][3] * invA1);
        *(float2*)&oB0[n0 * 8 + 2 * tig] =
            make_float2(oaccB[n0][0] * invB0, oaccB[n0][1] * invB0);
        *(float2*)&oB1[n0 * 8 + 2 * tig] =
            make_float2(oaccB[n0][2] * invB1, oaccB[n0][3] * invB1);
    }
}

// ---------------------------------------------------------------------------
extern "C" void kernel_launch(void* const* d_in, const int* in_sizes, int n_in,
                              void* d_out, int out_size) {
    const float* q    = (const float*)d_in[0];
    const float* k    = (const float*)d_in[1];
    const float* v    = (const float*)d_in[2];
    const void*  mask = d_in[3];
    const float* taus = (const float*)d_in[4];
    const float* bias = (const float*)d_in[5];
    float*       out  = (float*)d_out;
    (void)in_sizes; (void)n_in; (void)out_size;

    const int smem_bytes = SMEM_FLOATS * 4;
    cudaFuncSetAttribute(attn_kernel, cudaFuncAttributeMaxDynamicSharedMemorySize,
                         smem_bytes);

    detect_mask_kernel<<<1, 256>>>((const unsigned int*)mask);
    expand_mask_kernel<<<(Bb * Ss + 255) / 256, 256>>>(mask);

    dim3 grid(Ss / BM, Hh, Bb);
    attn_kernel<<<grid, NTHREADS, smem_bytes>>>(q, k, v, taus, bias, out);
}

// round 11
// speedup vs baseline: 1.4513x; 1.4513x over previous
#include <cuda_runtime.h>
#include <float.h>
#include <stdint.h>

#define Bb 2
#define Hh 16
#define Ss 2048
#define Dd 64
#define BM 128          // query rows per CTA (4 warps x 32 rows)
#define BN 64           // key tile
#define NTHREADS 128
#define NTILES (Ss / BN)   // 32

// ---- shared memory layout (32-bit word offsets) ----
// K frags: [kg(8)][lane(32)][12]  (8 u32 payload + 4 pad; stride 12 -> the 8
//          lanes of each LDS.128 phase hit all 32 banks: 12*l mod 32 distinct)
// V frags: [kgpair(4)][lane(32)][20] (16 u32 payload + 4 pad; stride 20 ditto)
#define KLST 12
#define VLST 20
#define KGSZ (32 * KLST)                 // 384 u32 per key-group
#define VPSZ (32 * VLST)                 // 640 u32 per key-pair-group
#define OFF_MASK 0                       // [2048] additive mask row (f32)
#define OFF_K    2048                    // 8*384  = 3072 u32
#define OFF_V    (OFF_K + 8 * KGSZ)      // 5120: 4*640 = 2560 u32
#define SMEM_WORDS (OFF_V + 4 * VPSZ)    // 7680 u32 = 30720 B

// ---------------------------------------------------------------------------
// helpers
// ---------------------------------------------------------------------------
__device__ __forceinline__ uint32_t h2(float lo, float hi) {
    uint32_t r;
    asm("cvt.rn.f16x2.f32 %0, %1, %2;" : "=r"(r) : "f"(hi), "f"(lo));
    return r;
}

// D += A*B, m16n8k16 f16 inputs, f32 accumulate (PTX fragment layouts)
__device__ __forceinline__ void mma16(float* d, const uint32_t* a,
                                      uint32_t b0, uint32_t b1) {
    asm volatile(
        "mma.sync.aligned.m16n8k16.row.col.f32.f16.f16.f32 "
        "{%0,%1,%2,%3},{%4,%5,%6,%7},{%8,%9},{%0,%1,%2,%3};"
        : "+f"(d[0]), "+f"(d[1]), "+f"(d[2]), "+f"(d[3])
        : "r"(a[0]), "r"(a[1]), "r"(a[2]), "r"(a[3]), "r"(b0), "r"(b1));
}

// ---------------------------------------------------------------------------
// Mask prepass: single-block kernel (detect dtype, then expand to additive).
// jax bool may arrive byte-bool or int32; byte case = 1024 u32 words, all
// scanned; a random 0/1 byte-bool buffer yields some word >1 a.s.
// ---------------------------------------------------------------------------
__device__ float g_maskadd[Bb * Ss];

__global__ void mask_prep_kernel(const void* __restrict__ mask) {
    __shared__ int bad;
    if (threadIdx.x == 0) bad = 0;
    __syncthreads();
    const unsigned int* mw = (const unsigned int*)mask;
    for (int idx = threadIdx.x; idx < (Bb * Ss) / 4; idx += blockDim.x)
        if (mw[idx] > 1u) bad = 1;
    __syncthreads();
    const int is32 = bad ? 0 : 1;
    for (int idx = threadIdx.x; idx < Bb * Ss; idx += blockDim.x) {
        int mval = is32 ? ((const int*)mask)[idx]
                        : (int)((const unsigned char*)mask)[idx];
        g_maskadd[idx] = mval ? 0.0f : -FLT_MAX;
    }
}

// ---------------------------------------------------------------------------
// Main attention kernel: fp16 m16n8k16 pipeline. 32 rows/warp (A/B blocks).
// P (MMA1 D-frag) packs DIRECTLY into MMA2's A-frag: two consecutive 8-key
// groups supply {a0,a1} and {a2,a3} — no shuffles, no permutation.
// ---------------------------------------------------------------------------
__global__ void __launch_bounds__(NTHREADS)
attn_kernel(const float* __restrict__ q,
            const float* __restrict__ k,
            const float* __restrict__ v,
            const float* __restrict__ taus,
            const float* __restrict__ bias,
            float* __restrict__ out)
{
    extern __shared__ float s[];
    uint32_t* su = (uint32_t*)s;

    const int tid  = threadIdx.x;
    const int wid  = tid >> 5;
    const int lane = tid & 31;
    const int g    = lane >> 2;    // groupID
    const int tig  = lane & 3;     // threadID_in_group

    const int itile = blockIdx.x;
    const int h     = blockIdx.y;
    const int b     = blockIdx.z;

    const int   plane = (b * Hh + h) * Ss;
    const float tau   = taus[h];
    const int   rowb  = wid * 32;
    const int   qgA   = itile * BM + rowb + g;   // row-block A, g-half row
    const int   qgB   = qgA + 16;                // row-block B

    // ---- stage mask row ----
    {
        const float* madd = g_maskadd + b * Ss;
        for (int x = tid; x < Ss; x += NTHREADS) s[OFF_MASK + x] = madd[x];
    }

    // ---- Q fragments (f16x2), loaded once from gmem ----
    // chunk k0 covers features [16k0,16k0+16): a0=row g cols 2t,2t+1;
    // a1=row g+8 same; a2=row g cols 2t+8,2t+9; a3=row g+8 same.
    uint32_t qfA[4][4], qfB[4][4];
    {
        const float* qa0 = q + (size_t)(plane + qgA) * Dd;
        const float* qa1 = qa0 + 8 * Dd;
        const float* qb0 = q + (size_t)(plane + qgB) * Dd;
        const float* qb1 = qb0 + 8 * Dd;
#pragma unroll
        for (int k0 = 0; k0 < 4; k0++) {
            const int f = 16 * k0 + 2 * tig;
            qfA[k0][0] = h2(qa0[f],     qa0[f + 1]);
            qfA[k0][1] = h2(qa1[f],     qa1[f + 1]);
            qfA[k0][2] = h2(qa0[f + 8], qa0[f + 9]);
            qfA[k0][3] = h2(qa1[f + 8], qa1[f + 9]);
            qfB[k0][0] = h2(qb0[f],     qb0[f + 1]);
            qfB[k0][1] = h2(qb1[f],     qb1[f + 1]);
            qfB[k0][2] = h2(qb0[f + 8], qb0[f + 9]);
            qfB[k0][3] = h2(qb1[f + 8], qb1[f + 9]);
        }
    }

    float oaccA[8][4], oaccB[8][4];
#pragma unroll
    for (int n0 = 0; n0 < 8; n0++)
#pragma unroll
        for (int x = 0; x < 4; x++) { oaccA[n0][x] = 0.f; oaccB[n0][x] = 0.f; }
    float lA0 = 0.f, lA1 = 0.f, lB0 = 0.f, lB1 = 0.f;

    const float4* ksrc = (const float4*)(k + (size_t)plane * Dd);
    const float4* vsrc = (const float4*)(v + (size_t)plane * Dd);
    const float* browA0 = bias + ((size_t)b * Ss + qgA) * Ss;
    const float* browA1 = browA0 + 8 * Ss;
    const float* browB0 = browA0 + 16 * Ss;
    const float* browB1 = browA0 + 24 * Ss;

    // ---- prefetch tile 0 into registers ----
    // K: linear float4 tasks. V: key-PAIR tasks (rows 2kp,2kp+1, col-quad c4)
    float4 kbuf[8], vbuf[8];
#pragma unroll
    for (int it = 0; it < 8; it++) kbuf[it] = ksrc[tid + it * NTHREADS];
#pragma unroll
    for (int it = 0; it < 4; it++) {
        const int task = tid + it * NTHREADS;
        const int kp = task >> 4, c4 = task & 15;
        vbuf[2 * it]     = vsrc[(2 * kp) * 16 + c4];
        vbuf[2 * it + 1] = vsrc[(2 * kp + 1) * 16 + c4];
    }

    for (int t = 0; t < NTILES; t++) {
        // ---- scatter buffered tile into fragment-packed f16x2 layout ----
        // K[key][f]: kg=key>>3; lane=(key&7)*4+((f&7)>>1); slot=(f>>4)*2+((f>>3)&1)
#pragma unroll
        for (int it = 0; it < 8; it++) {
            const int idx = tid + it * NTHREADS;
            const int key = idx >> 4, f = (idx & 15) * 4;
            const int kg = key >> 3;
            const int lane0 = (key & 7) * 4 + ((f & 7) >> 1);
            const int slot  = (f >> 4) * 2 + ((f >> 3) & 1);
            uint32_t* kb = &su[OFF_K + kg * KGSZ + slot];
            kb[lane0 * KLST]       = h2(kbuf[it].x, kbuf[it].y);
            kb[(lane0 + 1) * KLST] = h2(kbuf[it].z, kbuf[it].w);
        }
        // V keypair (2kp,2kp+1) col cc: kgpair=kp>>3; lane=(cc&7)*4+(kp&3);
        // slot=(cc>>3)*2+((kp>>2)&1); f16x2 low = even key.
#pragma unroll
        for (int it = 0; it < 4; it++) {
            const int task = tid + it * NTHREADS;
            const int kp = task >> 4, c = (task & 15) * 4;
            const int kgp = kp >> 3, tv = kp & 3, hi = (kp >> 2) & 1;
            const float4 v0 = vbuf[2 * it], v1 = vbuf[2 * it + 1];
            uint32_t* vb = &su[OFF_V + kgp * VPSZ + (c >> 3) * 2 + hi];
            const int lane0 = (c & 7) * 4 + tv;
            vb[lane0 * VLST]        = h2(v0.x, v1.x);
            vb[(lane0 + 4) * VLST]  = h2(v0.y, v1.y);
            vb[(lane0 + 8) * VLST]  = h2(v0.z, v1.z);
            vb[(lane0 + 12) * VLST] = h2(v0.w, v1.w);
        }
        __syncthreads();

        // ---- prefetch NEXT tile ----
        if (t + 1 < NTILES) {
            const int base = (t + 1) * BN * 16;
#pragma unroll
            for (int it = 0; it < 8; it++)
                kbuf[it] = ksrc[base + tid + it * NTHREADS];
#pragma unroll
            for (int it = 0; it < 4; it++) {
                const int task = tid + it * NTHREADS;
                const int kp = task >> 4, c4 = task & 15;
                vbuf[2 * it]     = vsrc[base + (2 * kp) * 16 + c4];
                vbuf[2 * it + 1] = vsrc[base + (2 * kp + 1) * 16 + c4];
            }
        }

        const int j0 = t * BN;

        // ---- stream over 4 key-pair-groups (16 keys each) ----
#pragma unroll
        for (int kgp = 0; kgp < 4; kgp++) {
            uint32_t aA[4], aB[4];

            // -- two 8-key halves: MMA1 + softmax; pack P into A-frag --
#pragma unroll
            for (int half = 0; half < 2; half++) {
                const int kg = 2 * kgp + half;

                // K fragments: 2x LDS.128, conflict-free
                uint32_t kfr[8];
                {
                    const uint4* kp4 =
                        (const uint4*)&su[OFF_K + kg * KGSZ + lane * KLST];
                    *(uint4*)&kfr[0] = kp4[0];
                    *(uint4*)&kfr[4] = kp4[1];
                }

                // MMA1: S(32x8) = Q(32x64) @ K_kg^T  (4 K-steps of 16)
                float saA[4] = {0.f, 0.f, 0.f, 0.f};
                float saB[4] = {0.f, 0.f, 0.f, 0.f};
#pragma unroll
                for (int k0 = 0; k0 < 4; k0++) {
                    mma16(saA, qfA[k0], kfr[2 * k0], kfr[2 * k0 + 1]);
                    mma16(saB, qfB[k0], kfr[2 * k0], kfr[2 * k0 + 1]);
                }

                // softmax: scale + mask + tau*bias + exp
                const int jgl = j0 + kg * 8 + tig * 2;
                float2 mk   = *(const float2*)&s[OFF_MASK + jgl];
                float2 biA0 = *(const float2*)&browA0[jgl];
                float2 biA1 = *(const float2*)&browA1[jgl];
                float2 biB0 = *(const float2*)&browB0[jgl];
                float2 biB1 = *(const float2*)&browB1[jgl];
                // masked: x*0.125+(-FLT_MAX) -> -FLT_MAX; __expf(-FLT_MAX)==0
                float pA0 = __expf(fmaf(saA[0], 0.125f, mk.x) - tau * biA0.x);
                float pA1 = __expf(fmaf(saA[1], 0.125f, mk.y) - tau * biA0.y);
                float pA2 = __expf(fmaf(saA[2], 0.125f, mk.x) - tau * biA1.x);
                float pA3 = __expf(fmaf(saA[3], 0.125f, mk.y) - tau * biA1.y);
                float pB0 = __expf(fmaf(saB[0], 0.125f, mk.x) - tau * biB0.x);
                float pB1 = __expf(fmaf(saB[1], 0.125f, mk.y) - tau * biB0.y);
                float pB2 = __expf(fmaf(saB[2], 0.125f, mk.x) - tau * biB1.x);
                float pB3 = __expf(fmaf(saB[3], 0.125f, mk.y) - tau * biB1.y);
                lA0 += pA0 + pA1;  lA1 += pA2 + pA3;
                lB0 += pB0 + pB1;  lB1 += pB2 + pB3;

                // D-frag -> A-frag: a[2*half+0] = rows g  cols 2t,2t+1 (+8*half)
                //                   a[2*half+1] = rows g+8 (f16x2 pack)
                aA[2 * half]     = h2(pA0, pA1);
                aA[2 * half + 1] = h2(pA2, pA3);
                aB[2 * half]     = h2(pB0, pB1);
                aB[2 * half + 1] = h2(pB2, pB3);
            }

            // V fragments: 4x LDS.128, conflict-free
            uint32_t vfr[16];
            {
                const uint4* vp4 =
                    (const uint4*)&su[OFF_V + kgp * VPSZ + lane * VLST];
                *(uint4*)&vfr[0]  = vp4[0];
                *(uint4*)&vfr[4]  = vp4[1];
                *(uint4*)&vfr[8]  = vp4[2];
                *(uint4*)&vfr[12] = vp4[3];
            }

            // MMA2: O(32x64) += P(32x16) @ V(16x64)
#pragma unroll
            for (int n0 = 0; n0 < 8; n0++) {
                mma16(oaccA[n0], aA, vfr[2 * n0], vfr[2 * n0 + 1]);
                mma16(oaccB[n0], aB, vfr[2 * n0], vfr[2 * n0 + 1]);
            }
        }
        __syncthreads();   // all warps done with K/V before restage
    }

    // ---- reduce l across the 4 lanes sharing each row ----
    lA0 += __shfl_xor_sync(0xffffffffu, lA0, 1);
    lA0 += __shfl_xor_sync(0xffffffffu, lA0, 2);
    lA1 += __shfl_xor_sync(0xffffffffu, lA1, 1);
    lA1 += __shfl_xor_sync(0xffffffffu, lA1, 2);
    lB0 += __shfl_xor_sync(0xffffffffu, lB0, 1);
    lB0 += __shfl_xor_sync(0xffffffffu, lB0, 2);
    lB1 += __shfl_xor_sync(0xffffffffu, lB1, 1);
    lB1 += __shfl_xor_sync(0xffffffffu, lB1, 2);
    const float invA0 = 1.0f / lA0;
    const float invA1 = 1.0f / lA1;
    const float invB0 = 1.0f / lB0;
    const float invB1 = 1.0f / lB1;

    // ---- normalize + write O ----
    float* oA0 = out + (size_t)(plane + qgA) * Dd;
    float* oA1 = oA0 + 8 * Dd;
    float* oB0 = out + (size_t)(plane + qgB) * Dd;
    float* oB1 = oB0 + 8 * Dd;
#pragma unroll
    for (int n0 = 0; n0 < 8; n0++) {
        *(float2*)&oA0[n0 * 8 + 2 * tig] =
            make_float2(oaccA[n0][0] * invA0, oaccA[n0][1] * invA0);
        *(float2*)&oA1[n0 * 8 + 2 * tig] =
            make_float2(oaccA[n0][2] * invA1, oaccA[n0][3] * invA1);
        *(float2*)&oB0[n0 * 8 + 2 * tig] =
            make_float2(oaccB[n0][0] * invB0, oaccB[n0][1] * invB0);
        *(float2*)&oB1[n0 * 8 + 2 * tig] =
            make_float2(oaccB[n0][2] * invB1, oaccB[n0][3] * invB1);
    }
}

// ---------------------------------------------------------------------------
extern "C" void kernel_launch(void* const* d_in, const int* in_sizes, int n_in,
                              void* d_out, int out_size) {
    const float* q    = (const float*)d_in[0];
    const float* k    = (const float*)d_in[1];
    const float* v    = (const float*)d_in[2];
    const void*  mask = d_in[3];
    const float* taus = (const float*)d_in[4];
    const float* bias = (const float*)d_in[5];
    float*       out  = (float*)d_out;
    (void)in_sizes; (void)n_in; (void)out_size;

    const int smem_bytes = SMEM_WORDS * 4;
    cudaFuncSetAttribute(attn_kernel, cudaFuncAttributeMaxDynamicSharedMemorySize,
                         smem_bytes);

    mask_prep_kernel<<<1, 256>>>(mask);

    dim3 grid(Ss / BM, Hh, Bb);
    attn_kernel<<<grid, NTHREADS, smem_bytes>>>(q, k, v, taus, bias, out);
}

// round 13
// speedup vs baseline: 1.4663x; 1.0104x over previous
#include <cuda_runtime.h>
#include <float.h>
#include <stdint.h>

#define Bb 2
#define Hh 16
#define Ss 2048
#define Dd 64
#define BM 128          // query rows per CTA (4 warps x 32 rows)
#define BN 64           // key tile
#define NTHREADS 128
#define NTILES (Ss / BN)   // 32

// ---- shared memory layout (32-bit word offsets) ----
// K frags: [kg(8)][lane(32)][12]  (8 u32 payload + 4 pad; stride 12 -> the 8
//          lanes of each LDS.128 phase hit all 32 banks: 12*l mod 32 distinct)
// V frags: [kgpair(4)][lane(32)][20] (16 u32 payload + 4 pad; stride 20 ditto)
#define KLST 12
#define VLST 20
#define KGSZ (32 * KLST)                 // 384 u32 per key-group
#define VPSZ (32 * VLST)                 // 640 u32 per key-pair-group
#define OFF_MASK 0                       // [2048] additive mask row (f32)
#define OFF_K    2048                    // 8*384  = 3072 u32
#define OFF_V    (OFF_K + 8 * KGSZ)      // 5120: 4*640 = 2560 u32
#define SMEM_WORDS (OFF_V + 4 * VPSZ)    // 7680 u32 = 30720 B

// ---------------------------------------------------------------------------
// helpers
// ---------------------------------------------------------------------------
__device__ __forceinline__ uint32_t h2(float lo, float hi) {
    uint32_t r;
    asm("cvt.rn.f16x2.f32 %0, %1, %2;" : "=r"(r) : "f"(hi), "f"(lo));
    return r;
}

// D += A*B, m16n8k16 f16 inputs, f32 accumulate (PTX fragment layouts)
__device__ __forceinline__ void mma16(float* d, const uint32_t* a,
                                      uint32_t b0, uint32_t b1) {
    asm volatile(
        "mma.sync.aligned.m16n8k16.row.col.f32.f16.f16.f32 "
        "{%0,%1,%2,%3},{%4,%5,%6,%7},{%8,%9},{%0,%1,%2,%3};"
        : "+f"(d[0]), "+f"(d[1]), "+f"(d[2]), "+f"(d[3])
        : "r"(a[0]), "r"(a[1]), "r"(a[2]), "r"(a[3]), "r"(b0), "r"(b1));
}

// ---------------------------------------------------------------------------
// Mask prepass: single-block kernel (detect dtype, then expand to additive).
// jax bool may arrive byte-bool or int32; byte case = 1024 u32 words, all
// scanned; a random 0/1 byte-bool buffer yields some word >1 a.s.
// ---------------------------------------------------------------------------
__device__ float g_maskadd[Bb * Ss];

__global__ void mask_prep_kernel(const void* __restrict__ mask) {
    __shared__ int bad;
    if (threadIdx.x == 0) bad = 0;
    __syncthreads();
    const unsigned int* mw = (const unsigned int*)mask;
    for (int idx = threadIdx.x; idx < (Bb * Ss) / 4; idx += blockDim.x)
        if (mw[idx] > 1u) bad = 1;
    __syncthreads();
    const int is32 = bad ? 0 : 1;
    for (int idx = threadIdx.x; idx < Bb * Ss; idx += blockDim.x) {
        int mval = is32 ? ((const int*)mask)[idx]
                        : (int)((const unsigned char*)mask)[idx];
        g_maskadd[idx] = mval ? 0.0f : -FLT_MAX;
    }
}

// ---------------------------------------------------------------------------
// Main attention kernel: fp16 m16n8k16 pipeline. 32 rows/warp (A/B blocks).
// P (MMA1 D-frag) packs DIRECTLY into MMA2's A-frag: two consecutive 8-key
// groups supply {a0,a1} and {a2,a3} — no shuffles, no permutation.
// ---------------------------------------------------------------------------
__global__ void __launch_bounds__(NTHREADS)
attn_kernel(const float* __restrict__ q,
            const float* __restrict__ k,
            const float* __restrict__ v,
            const float* __restrict__ taus,
            const float* __restrict__ bias,
            float* __restrict__ out)
{
    extern __shared__ float s[];
    uint32_t* su = (uint32_t*)s;

    const int tid  = threadIdx.x;
    const int wid  = tid >> 5;
    const int lane = tid & 31;
    const int g    = lane >> 2;    // groupID
    const int tig  = lane & 3;     // threadID_in_group

    const int itile = blockIdx.x;
    const int h     = blockIdx.y;
    const int b     = blockIdx.z;

    const int   plane = (b * Hh + h) * Ss;
    const float tau   = taus[h];
    const int   rowb  = wid * 32;
    const int   qgA   = itile * BM + rowb + g;   // row-block A, g-half row
    const int   qgB   = qgA + 16;                // row-block B

    // ---- stage mask row ----
    {
        const float* madd = g_maskadd + b * Ss;
        for (int x = tid; x < Ss; x += NTHREADS) s[OFF_MASK + x] = madd[x];
    }

    // ---- Q fragments (f16x2), loaded once from gmem ----
    // chunk k0 covers features [16k0,16k0+16): a0=row g cols 2t,2t+1;
    // a1=row g+8 same; a2=row g cols 2t+8,2t+9; a3=row g+8 same.
    uint32_t qfA[4][4], qfB[4][4];
    {
        const float* qa0 = q + (size_t)(plane + qgA) * Dd;
        const float* qa1 = qa0 + 8 * Dd;
        const float* qb0 = q + (size_t)(plane + qgB) * Dd;
        const float* qb1 = qb0 + 8 * Dd;
#pragma unroll
        for (int k0 = 0; k0 < 4; k0++) {
            const int f = 16 * k0 + 2 * tig;
            qfA[k0][0] = h2(qa0[f],     qa0[f + 1]);
            qfA[k0][1] = h2(qa1[f],     qa1[f + 1]);
            qfA[k0][2] = h2(qa0[f + 8], qa0[f + 9]);
            qfA[k0][3] = h2(qa1[f + 8], qa1[f + 9]);
            qfB[k0][0] = h2(qb0[f],     qb0[f + 1]);
            qfB[k0][1] = h2(qb1[f],     qb1[f + 1]);
            qfB[k0][2] = h2(qb0[f + 8], qb0[f + 9]);
            qfB[k0][3] = h2(qb1[f + 8], qb1[f + 9]);
        }
    }

    float oaccA[8][4], oaccB[8][4];
#pragma unroll
    for (int n0 = 0; n0 < 8; n0++)
#pragma unroll
        for (int x = 0; x < 4; x++) { oaccA[n0][x] = 0.f; oaccB[n0][x] = 0.f; }
    float lA0 = 0.f, lA1 = 0.f, lB0 = 0.f, lB1 = 0.f;

    const float4* ksrc = (const float4*)(k + (size_t)plane * Dd);
    const float4* vsrc = (const float4*)(v + (size_t)plane * Dd);
    const float* browA0 = bias + ((size_t)b * Ss + qgA) * Ss;
    const float* browA1 = browA0 + 8 * Ss;
    const float* browB0 = browA0 + 16 * Ss;
    const float* browB1 = browA0 + 24 * Ss;

    // ---- prefetch tile 0 into registers ----
    // K: linear float4 tasks. V: key-PAIR tasks (rows 2kp,2kp+1, col-quad c4)
    float4 kbuf[8], vbuf[8];
#pragma unroll
    for (int it = 0; it < 8; it++) kbuf[it] = ksrc[tid + it * NTHREADS];
#pragma unroll
    for (int it = 0; it < 4; it++) {
        const int task = tid + it * NTHREADS;
        const int kp = task >> 4, c4 = task & 15;
        vbuf[2 * it]     = vsrc[(2 * kp) * 16 + c4];
        vbuf[2 * it + 1] = vsrc[(2 * kp + 1) * 16 + c4];
    }

    for (int t = 0; t < NTILES; t++) {
        // ---- scatter buffered tile into fragment-packed f16x2 layout ----
        // K[key][f]: kg=key>>3; lane=(key&7)*4+((f&7)>>1); slot=(f>>4)*2+((f>>3)&1)
#pragma unroll
        for (int it = 0; it < 8; it++) {
            const int idx = tid + it * NTHREADS;
            const int key = idx >> 4, f = (idx & 15) * 4;
            const int kg = key >> 3;
            const int lane0 = (key & 7) * 4 + ((f & 7) >> 1);
            const int slot  = (f >> 4) * 2 + ((f >> 3) & 1);
            uint32_t* kb = &su[OFF_K + kg * KGSZ + slot];
            kb[lane0 * KLST]       = h2(kbuf[it].x, kbuf[it].y);
            kb[(lane0 + 1) * KLST] = h2(kbuf[it].z, kbuf[it].w);
        }
        // V keypair (2kp,2kp+1) col cc: kgpair=kp>>3; lane=(cc&7)*4+(kp&3);
        // slot=(cc>>3)*2+((kp>>2)&1); f16x2 low = even key.
#pragma unroll
        for (int it = 0; it < 4; it++) {
            const int task = tid + it * NTHREADS;
            const int kp = task >> 4, c = (task & 15) * 4;
            const int kgp = kp >> 3, tv = kp & 3, hi = (kp >> 2) & 1;
            const float4 v0 = vbuf[2 * it], v1 = vbuf[2 * it + 1];
            uint32_t* vb = &su[OFF_V + kgp * VPSZ + (c >> 3) * 2 + hi];
            const int lane0 = (c & 7) * 4 + tv;
            vb[lane0 * VLST]        = h2(v0.x, v1.x);
            vb[(lane0 + 4) * VLST]  = h2(v0.y, v1.y);
            vb[(lane0 + 8) * VLST]  = h2(v0.z, v1.z);
            vb[(lane0 + 12) * VLST] = h2(v0.w, v1.w);
        }
        __syncthreads();

        // ---- prefetch NEXT tile ----
        if (t + 1 < NTILES) {
            const int base = (t + 1) * BN * 16;
#pragma unroll
            for (int it = 0; it < 8; it++)
                kbuf[it] = ksrc[base + tid + it * NTHREADS];
#pragma unroll
            for (int it = 0; it < 4; it++) {
                const int task = tid + it * NTHREADS;
                const int kp = task >> 4, c4 = task & 15;
                vbuf[2 * it]     = vsrc[base + (2 * kp) * 16 + c4];
                vbuf[2 * it + 1] = vsrc[base + (2 * kp + 1) * 16 + c4];
            }
        }

        const int j0 = t * BN;

        // ---- stream over 4 key-pair-groups (16 keys each) ----
#pragma unroll
        for (int kgp = 0; kgp < 4; kgp++) {
            uint32_t aA[4], aB[4];

            // -- two 8-key halves: MMA1 + softmax; pack P into A-frag --
#pragma unroll
            for (int half = 0; half < 2; half++) {
                const int kg = 2 * kgp + half;

                // K fragments: 2x LDS.128, conflict-free
                uint32_t kfr[8];
                {
                    const uint4* kp4 =
                        (const uint4*)&su[OFF_K + kg * KGSZ + lane * KLST];
                    *(uint4*)&kfr[0] = kp4[0];
                    *(uint4*)&kfr[4] = kp4[1];
                }

                // MMA1: S(32x8) = Q(32x64) @ K_kg^T  (4 K-steps of 16)
                float saA[4] = {0.f, 0.f, 0.f, 0.f};
                float saB[4] = {0.f, 0.f, 0.f, 0.f};
#pragma unroll
                for (int k0 = 0; k0 < 4; k0++) {
                    mma16(saA, qfA[k0], kfr[2 * k0], kfr[2 * k0 + 1]);
                    mma16(saB, qfB[k0], kfr[2 * k0], kfr[2 * k0 + 1]);
                }

                // softmax: scale + mask + tau*bias + exp
                const int jgl = j0 + kg * 8 + tig * 2;
                float2 mk   = *(const float2*)&s[OFF_MASK + jgl];
                float2 biA0 = *(const float2*)&browA0[jgl];
                float2 biA1 = *(const float2*)&browA1[jgl];
                float2 biB0 = *(const float2*)&browB0[jgl];
                float2 biB1 = *(const float2*)&browB1[jgl];
                // masked: x*0.125+(-FLT_MAX) -> -FLT_MAX; __expf(-FLT_MAX)==0
                float pA0 = __expf(fmaf(saA[0], 0.125f, mk.x) - tau * biA0.x);
                float pA1 = __expf(fmaf(saA[1], 0.125f, mk.y) - tau * biA0.y);
                float pA2 = __expf(fmaf(saA[2], 0.125f, mk.x) - tau * biA1.x);
                float pA3 = __expf(fmaf(saA[3], 0.125f, mk.y) - tau * biA1.y);
                float pB0 = __expf(fmaf(saB[0], 0.125f, mk.x) - tau * biB0.x);
                float pB1 = __expf(fmaf(saB[1], 0.125f, mk.y) - tau * biB0.y);
                float pB2 = __expf(fmaf(saB[2], 0.125f, mk.x) - tau * biB1.x);
                float pB3 = __expf(fmaf(saB[3], 0.125f, mk.y) - tau * biB1.y);
                lA0 += pA0 + pA1;  lA1 += pA2 + pA3;
                lB0 += pB0 + pB1;  lB1 += pB2 + pB3;

                // D-frag -> A-frag: a[2*half+0] = rows g  cols 2t,2t+1 (+8*half)
                //                   a[2*half+1] = rows g+8 (f16x2 pack)
                aA[2 * half]     = h2(pA0, pA1);
                aA[2 * half + 1] = h2(pA2, pA3);
                aB[2 * half]     = h2(pB0, pB1);
                aB[2 * half + 1] = h2(pB2, pB3);
            }

            // V fragments: 4x LDS.128, conflict-free
            uint32_t vfr[16];
            {
                const uint4* vp4 =
                    (const uint4*)&su[OFF_V + kgp * VPSZ + lane * VLST];
                *(uint4*)&vfr[0]  = vp4[0];
                *(uint4*)&vfr[4]  = vp4[1];
                *(uint4*)&vfr[8]  = vp4[2];
                *(uint4*)&vfr[12] = vp4[3];
            }

            // MMA2: O(32x64) += P(32x16) @ V(16x64)
#pragma unroll
            for (int n0 = 0; n0 < 8; n0++) {
                mma16(oaccA[n0], aA, vfr[2 * n0], vfr[2 * n0 + 1]);
                mma16(oaccB[n0], aB, vfr[2 * n0], vfr[2 * n0 + 1]);
            }
        }
        __syncthreads();   // all warps done with K/V before restage
    }

    // ---- reduce l across the 4 lanes sharing each row ----
    lA0 += __shfl_xor_sync(0xffffffffu, lA0, 1);
    lA0 += __shfl_xor_sync(0xffffffffu, lA0, 2);
    lA1 += __shfl_xor_sync(0xffffffffu, lA1, 1);
    lA1 += __shfl_xor_sync(0xffffffffu, lA1, 2);
    lB0 += __shfl_xor_sync(0xffffffffu, lB0, 1);
    lB0 += __shfl_xor_sync(0xffffffffu, lB0, 2);
    lB1 += __shfl_xor_sync(0xffffffffu, lB1, 1);
    lB1 += __shfl_xor_sync(0xffffffffu, lB1, 2);
    const float invA0 = 1.0f / lA0;
    const float invA1 = 1.0f / lA1;
    const float invB0 = 1.0f / lB0;
    const float invB1 = 1.0f / lB1;

    // ---- normalize + write O ----
    float* oA0 = out + (size_t)(plane + qgA) * Dd;
    float* oA1 = oA0 + 8 * Dd;
    float* oB0 = out + (size_t)(plane + qgB) * Dd;
    float* oB1 = oB0 + 8 * Dd;
#pragma unroll
    for (int n0 = 0; n0 < 8; n0++) {
        *(float2*)&oA0[n0 * 8 + 2 * tig] =
            make_float2(oaccA[n0][0] * invA0, oaccA[n0][1] * invA0);
        *(float2*)&oA1[n0 * 8 + 2 * tig] =
            make_float2(oaccA[n0][2] * invA1, oaccA[n0][3] * invA1);
        *(float2*)&oB0[n0 * 8 + 2 * tig] =
            make_float2(oaccB[n0][0] * invB0, oaccB[n0][1] * invB0);
        *(float2*)&oB1[n0 * 8 + 2 * tig] =
            make_float2(oaccB[n0][2] * invB1, oaccB[n0][3] * invB1);
    }
}

// ---------------------------------------------------------------------------
extern "C" void kernel_launch(void* const* d_in, const int* in_sizes, int n_in,
                              void* d_out, int out_size) {
    const float* q    = (const float*)d_in[0];
    const float* k    = (const float*)d_in[1];
    const float* v    = (const float*)d_in[2];
    const void*  mask = d_in[3];
    const float* taus = (const float*)d_in[4];
    const float* bias = (const float*)d_in[5];
    float*       out  = (float*)d_out;
    (void)in_sizes; (void)n_in; (void)out_size;

    const int smem_bytes = SMEM_WORDS * 4;
    cudaFuncSetAttribute(attn_kernel, cudaFuncAttributeMaxDynamicSharedMemorySize,
                         smem_bytes);

    mask_prep_kernel<<<1, 1024>>>(mask);

    dim3 grid(Ss / BM, Hh, Bb);
    attn_kernel<<<grid, NTHREADS, smem_bytes>>>(q, k, v, taus, bias, out);
}